// round 3
// baseline (speedup 1.0000x reference)
#include <cuda_runtime.h>
#include <cuda_bf16.h>

#define NC   3144   // counties
#define TT   156    // time steps
#define TP   154    // predicted steps (T - p)
#define TPAD 160    // padded t dimension
#define NNZ  31440
#define CAP  128    // bucket capacity per column (Poisson(10), max ~35)

#define MT          128                 // counties per prep block
#define NMB         25                  // ceil(NC / MT)
#define TC          8                   // t-steps per prep chunk
#define NTC         (TPAD / TC)         // 20
#define PREP_BLOCKS (NMB * NTC)         // 500
#define SCAT_BLOCKS ((NNZ + 127) / 128) // 246

// -------- scratch (no allocations allowed; zero-initialized at load) --------
__device__ int    g_count[NC];
__device__ int    g_done[NC];           // arrival counter for counter re-arm
__device__ int4   g_meta[NC * CAP];     // {row, bv, av, hv} packed
__device__ float2 g_csd [NC * TPAD];    // {C[t]+C[t+1], D[t]+D[t+1]} at [m][t]
__device__ float2 g_base[NC * TPAD];    // {mob_c + ups@cov, mob_d + zeta@cov}

// ============================================================
// Kernel A: prep (lag sums + base terms, [m][t] layout, smem-
// transposed coalesced stores) fused with nnz bucket scatter.
// g_count is zero on entry (static init / re-armed by main).
// ============================================================
__global__ void prep_scatter_kernel(
    const float* __restrict__ C, const float* __restrict__ D,
    const float* __restrict__ M, const float* __restrict__ cov,
    const float* __restrict__ mu, const float* __restrict__ nu,
    const float* __restrict__ ups, const float* __restrict__ zeta,
    const float* __restrict__ bnz, const float* __restrict__ anz,
    const float* __restrict__ hnz, const int* __restrict__ rows,
    const int* __restrict__ cols)
{
    const int b = blockIdx.x;

    // ---------------- scatter blocks (first wave) ----------------
    if (b < SCAT_BLOCKS) {
        int k = b * 128 + threadIdx.x;
        if (k < NNZ) {
            int c = cols[k];
            int slot = atomicAdd(&g_count[c], 1);
            if (slot < CAP)
                g_meta[c * CAP + slot] = make_int4(
                    rows[k], __float_as_int(bnz[k]),
                    __float_as_int(anz[k]), __float_as_int(hnz[k]));
        }
        return;
    }

    // ---------------- prep blocks ----------------
    __shared__ float2 sc[TC][MT + 4];   // [t_local][m_local], pad vs conflicts
    __shared__ float2 sb[TC][MT + 4];

    const int pb = b - SCAT_BLOCKS;
    const int mblk = pb % NMB, tc = pb / NMB;
    const int tx = threadIdx.x;
    const int m0 = mblk * MT;
    const int m  = min(m0 + tx, NC - 1);   // clamp OOB lanes (stores guarded)
    const int t0 = tc * TC;

    // uniform small params
    float muv[12], nuv[12];
#pragma unroll
    for (int i = 0; i < 12; i++) { muv[i] = mu[i]; nuv[i] = nu[i]; }

    // covariate terms (t-independent)
    float cc = 0.f, cd = 0.f;
#pragma unroll
    for (int j = 0; j < 10; j++) {
        float cv = cov[j * NC + m];
        cc += ups[j]  * cv;
        cd += zeta[j] * cv;
    }

    // rotating "next" values: C/D/M each loaded exactly once per t
    float cn = C[t0 * NC + m];
    float dn = D[t0 * NC + m];
    float mn[6];
#pragma unroll
    for (int k = 0; k < 6; k++) mn[k] = M[(k * TT + t0) * NC + m];

#pragma unroll
    for (int j = 0; j < TC; j++) {
        int tn = min(t0 + j + 1, TT - 1);   // clamp: t>=154 lanes never stored
        float c0 = cn;  cn = C[tn * NC + m];
        float d0 = dn;  dn = D[tn * NC + m];
        float mc = cc, md = cd;
#pragma unroll
        for (int k = 0; k < 6; k++) {
            float v0 = mn[k];
            float v1 = M[(k * TT + tn) * NC + m];
            mn[k] = v1;
            mc += muv[k * 2] * v0 + muv[k * 2 + 1] * v1;
            md += nuv[k * 2] * v0 + nuv[k * 2 + 1] * v1;
        }
        sc[j][tx] = make_float2(c0 + cn, d0 + dn);
        sb[j][tx] = make_float2(mc, md);
    }
    __syncthreads();

    // coalesced stores: consecutive threads cover t fast, then m
#pragma unroll
    for (int j = 0; j < TC; j++) {
        int idx = j * MT + tx;             // 0..1023
        int ml = idx >> 3, tl = idx & 7;
        if (m0 + ml < NC) {
            g_csd [(m0 + ml) * TPAD + t0 + tl] = sc[tl][ml];
            g_base[(m0 + ml) * TPAD + t0 + tl] = sb[tl][ml];
        }
    }
}

// ============================================================
// Kernel B: sparse gather. grid (393, 5), block 256 (8 warps).
// warp w -> column m = bx*8 + w; blockIdx.y -> t-chunk of 32.
// ============================================================
__global__ void main_kernel(float* __restrict__ out)
{
    __shared__ int4   smeta[8][32];
    __shared__ float2 tile[32][9];        // [t_local][m_local]

    const int tid  = threadIdx.x;
    const int w    = tid >> 5, lane = tid & 31;
    const int m0   = blockIdx.x * 8;
    const int m    = m0 + w;
    const int tb   = blockIdx.y * 32;     // t base for this block

    // cooperative meta staging: each warp loads its column's first 32 slots
    smeta[w][lane] = g_meta[m * CAP + lane];

    const int cnt = g_count[m];           // broadcast
    __syncthreads();

    float2 bse = g_base[m * TPAD + tb + lane];
    float accC = bse.x, accD = bse.y;

    const int jn = min(cnt, 32);
#pragma unroll 4
    for (int j = 0; j < jn; j++) {
        int4 md = smeta[w][j];            // LDS broadcast
        float2 v = g_csd[md.x * TPAD + tb + lane];   // 256B coalesced
        float bv = __int_as_float(md.y);
        float av = __int_as_float(md.z);
        float hv = __int_as_float(md.w);
        accC += bv * v.x;
        accD += hv * v.x + av * v.y;
    }
    // rare tail (cnt > 32)
    for (int s = 32; s < cnt; s++) {
        int4 md = g_meta[m * CAP + min(s, CAP - 1)];
        float2 v = g_csd[md.x * TPAD + tb + lane];
        accC += __int_as_float(md.y) * v.x;
        accD += __int_as_float(md.w) * v.x + __int_as_float(md.z) * v.y;
    }

    // counter re-arm: 5 blocks read g_count[m]; last arrival zeroes it.
    if (lane == 0) {
        __threadfence();                  // order cnt load before arrival
        int old = atomicAdd(&g_done[m], 1);
        if (old == 4) { g_count[m] = 0; g_done[m] = 0; }
    }

    // transpose through smem, coalesced stores
    tile[lane][w] = make_float2(accC, accD);
    __syncthreads();

    const int t  = tid >> 3, mo = tid & 7;
    const int tg = tb + t;
    if (tg < TP) {
        float2 v = tile[t][mo];
        out[tg        * NC + m0 + mo] = v.x;
        out[(TP + tg) * NC + m0 + mo] = v.y;
    }
}

// ============================================================
extern "C" void kernel_launch(void* const* d_in, const int* in_sizes, int n_in,
                              void* d_out, int out_size)
{
    const float* C    = (const float*)d_in[0];
    const float* D    = (const float*)d_in[1];
    const float* M    = (const float*)d_in[2];
    const float* cov  = (const float*)d_in[3];
    const float* bnz  = (const float*)d_in[4];
    const float* anz  = (const float*)d_in[5];
    const float* hnz  = (const float*)d_in[6];
    const float* mu   = (const float*)d_in[7];
    const float* nu   = (const float*)d_in[8];
    const float* ups  = (const float*)d_in[9];
    const float* zeta = (const float*)d_in[10];
    const int*   rows = (const int*)d_in[11];
    const int*   cols = (const int*)d_in[12];
    float* out = (float*)d_out;

    prep_scatter_kernel<<<PREP_BLOCKS + SCAT_BLOCKS, MT>>>(
        C, D, M, cov, mu, nu, ups, zeta, bnz, anz, hnz, rows, cols);

    main_kernel<<<dim3(NC / 8, TPAD / 32), 256>>>(out);
}

// round 4
// speedup vs baseline: 1.3541x; 1.3541x over previous
#include <cuda_runtime.h>
#include <cuda_bf16.h>

#define NC   3144   // counties
#define TT   156    // time steps
#define TP   154    // predicted steps (T - p)
#define TPAD 160    // padded t dimension
#define NNZ  31440
#define CAP  128    // bucket capacity per column (Poisson(10), max ~35)

#define MT          256                 // counties per prep block (2 per thread)
#define NMB         13                  // ceil(NC / MT)
#define TC          4                   // t-steps per prep chunk
#define NTC         (TPAD / TC)         // 40
#define PREP_BLOCKS (NMB * NTC)         // 520
#define SCAT_BLOCKS ((NNZ + 127) / 128) // 246

// -------- scratch (no allocations allowed; zero-initialized at load) --------
__device__ int    g_count[NC];
__device__ int4   g_meta[NC * CAP];     // {row, bv, av, hv} packed
__device__ float2 g_csd [NC * TPAD];    // {C[t]+C[t+1], D[t]+D[t+1]} at [m][t]
__device__ float2 g_base[NC * TPAD];    // {mob_c + ups@cov, mob_d + zeta@cov}

// ============================================================
// Kernel A: prep (lag sums + base terms, [m][t] layout) fused
// with nnz bucket scatter. Each prep thread owns 2 adjacent
// counties (float2 loads) and TC=4 sequential t-steps.
// ============================================================
__global__ void prep_scatter_kernel(
    const float* __restrict__ C, const float* __restrict__ D,
    const float* __restrict__ M, const float* __restrict__ cov,
    const float* __restrict__ mu, const float* __restrict__ nu,
    const float* __restrict__ ups, const float* __restrict__ zeta,
    const float* __restrict__ bnz, const float* __restrict__ anz,
    const float* __restrict__ hnz, const int* __restrict__ rows,
    const int* __restrict__ cols)
{
    const int b = blockIdx.x;

    // ---------------- scatter blocks (first wave) ----------------
    if (b < SCAT_BLOCKS) {
        int k = b * 128 + threadIdx.x;
        if (k < NNZ) {
            int c = cols[k];
            int slot = atomicAdd(&g_count[c], 1);
            if (slot < CAP)
                g_meta[c * CAP + slot] = make_int4(
                    rows[k], __float_as_int(bnz[k]),
                    __float_as_int(anz[k]), __float_as_int(hnz[k]));
        }
        return;
    }

    // ---------------- prep blocks ----------------
    __shared__ float2 sc[MT][TC + 1];   // {cs, ds} per (county, t)
    __shared__ float2 sb[MT][TC + 1];   // {baseC, baseD}

    const int pb = b - SCAT_BLOCKS;
    const int mblk = pb % NMB, tcb = pb / NMB;
    const int tx = threadIdx.x;
    const int m0 = mblk * MT;
    const int mm = min(m0 + 2 * tx, NC - 2);   // even; float2-aligned
    const int t0 = tcb * TC;

    // uniform small params
    float muv[12], nuv[12];
#pragma unroll
    for (int i = 0; i < 12; i++) { muv[i] = mu[i]; nuv[i] = nu[i]; }

    // covariate terms (t-independent), 2 counties at once
    float ccx = 0.f, ccy = 0.f, cdx = 0.f, cdy = 0.f;
#pragma unroll
    for (int j = 0; j < 10; j++) {
        float2 cv = *(const float2*)&cov[j * NC + mm];
        ccx += ups[j]  * cv.x;  ccy += ups[j]  * cv.y;
        cdx += zeta[j] * cv.x;  cdy += zeta[j] * cv.y;
    }

    // rotating "next" values: C/D/M each loaded exactly once per t
    float2 cn = *(const float2*)&C[t0 * NC + mm];
    float2 dn = *(const float2*)&D[t0 * NC + mm];
    float2 mn[6];
#pragma unroll
    for (int k = 0; k < 6; k++) mn[k] = *(const float2*)&M[(k * TT + t0) * NC + mm];

#pragma unroll
    for (int j = 0; j < TC; j++) {
        int tn = min(t0 + j + 1, TT - 1);   // clamp: t>=154 never reaches output
        float2 c0 = cn;  cn = *(const float2*)&C[tn * NC + mm];
        float2 d0 = dn;  dn = *(const float2*)&D[tn * NC + mm];
        float mcx = ccx, mcy = ccy, mdx = cdx, mdy = cdy;
#pragma unroll
        for (int k = 0; k < 6; k++) {
            float2 v0 = mn[k];
            float2 v1 = *(const float2*)&M[(k * TT + tn) * NC + mm];
            mn[k] = v1;
            mcx += muv[k*2] * v0.x + muv[k*2+1] * v1.x;
            mcy += muv[k*2] * v0.y + muv[k*2+1] * v1.y;
            mdx += nuv[k*2] * v0.x + nuv[k*2+1] * v1.x;
            mdy += nuv[k*2] * v0.y + nuv[k*2+1] * v1.y;
        }
        sc[2*tx    ][j] = make_float2(c0.x + cn.x, d0.x + dn.x);
        sc[2*tx + 1][j] = make_float2(c0.y + cn.y, d0.y + dn.y);
        sb[2*tx    ][j] = make_float2(mcx, mdx);
        sb[2*tx + 1][j] = make_float2(mcy, mdy);
    }
    __syncthreads();

    // coalesced-ish stores: consecutive threads cover t fast, then m
#pragma unroll
    for (int i = 0; i < (MT * TC) / 128; i++) {      // 8 iters
        int idx = i * 128 + tx;                      // 0..1023
        int ml = idx >> 2, tl = idx & 3;
        if (m0 + ml < NC) {
            g_csd [(m0 + ml) * TPAD + t0 + tl] = sc[ml][tl];
            g_base[(m0 + ml) * TPAD + t0 + tl] = sb[ml][tl];
        }
    }
}

// ============================================================
// Kernel B: sparse gather. 393 blocks x 256 thr; warp = one
// column m over all 160 t. Meta prefetched via one coalesced
// int4 load into warp-private smem -> deep MLP in the nnz loop.
// ============================================================
__global__ void main_kernel(float* __restrict__ out)
{
    __shared__ int4   smeta[8][32];
    __shared__ float2 tile[TPAD][9];      // [t][m_local]

    const int tid  = threadIdx.x;
    const int w    = tid >> 5, lane = tid & 31;
    const int m0   = blockIdx.x * 8;
    const int m    = m0 + w;              // NC = 393*8 exact

    // prefetch: whole bucket header in one coalesced load
    int4 mymeta = g_meta[m * CAP + lane];
    int  cnt    = g_count[m];             // broadcast load (all lanes)
    smeta[w][lane] = mymeta;
    __syncwarp();
    if (lane == 0) g_count[m] = 0;        // re-arm for next graph replay

    float accC[5], accD[5];
#pragma unroll
    for (int i = 0; i < 5; i++) {
        float2 bv = g_base[m * TPAD + lane + 32 * i];
        accC[i] = bv.x;
        accD[i] = bv.y;
    }

    const int jn = min(cnt, 32);
#pragma unroll 2
    for (int j = 0; j < jn; j++) {
        int4 md = smeta[w][j];            // LDS broadcast, off critical path
        const float2* __restrict__ cr = &g_csd[md.x * TPAD + lane];
        float bv = __int_as_float(md.y);
        float av = __int_as_float(md.z);
        float hv = __int_as_float(md.w);
        float2 v0 = cr[0], v1 = cr[32], v2 = cr[64], v3 = cr[96], v4 = cr[128];
        accC[0] += bv * v0.x;  accD[0] += hv * v0.x + av * v0.y;
        accC[1] += bv * v1.x;  accD[1] += hv * v1.x + av * v1.y;
        accC[2] += bv * v2.x;  accD[2] += hv * v2.x + av * v2.y;
        accC[3] += bv * v3.x;  accD[3] += hv * v3.x + av * v3.y;
        accC[4] += bv * v4.x;  accD[4] += hv * v4.x + av * v4.y;
    }
    // rare tail (cnt > 32)
    for (int s = 32; s < cnt; s++) {
        int4 md = g_meta[m * CAP + min(s, CAP - 1)];
        const float2* __restrict__ cr = &g_csd[md.x * TPAD + lane];
        float bv = __int_as_float(md.y);
        float av = __int_as_float(md.z);
        float hv = __int_as_float(md.w);
#pragma unroll
        for (int i = 0; i < 5; i++) {
            float2 v = cr[32 * i];
            accC[i] += bv * v.x;
            accD[i] += hv * v.x + av * v.y;
        }
    }

    // transpose through smem, coalesced stores
#pragma unroll
    for (int i = 0; i < 5; i++)
        tile[lane + 32 * i][w] = make_float2(accC[i], accD[i]);
    __syncthreads();

#pragma unroll
    for (int j = 0; j < 10; j++) {
        int idx = tid + j * 256;          // < 2560
        int t = idx >> 3, mo = idx & 7;
        if (t < TP) {
            float2 v = tile[t][mo];
            out[t        * NC + m0 + mo] = v.x;
            out[(TP + t) * NC + m0 + mo] = v.y;
        }
    }
}

// ============================================================
extern "C" void kernel_launch(void* const* d_in, const int* in_sizes, int n_in,
                              void* d_out, int out_size)
{
    const float* C    = (const float*)d_in[0];
    const float* D    = (const float*)d_in[1];
    const float* M    = (const float*)d_in[2];
    const float* cov  = (const float*)d_in[3];
    const float* bnz  = (const float*)d_in[4];
    const float* anz  = (const float*)d_in[5];
    const float* hnz  = (const float*)d_in[6];
    const float* mu   = (const float*)d_in[7];
    const float* nu   = (const float*)d_in[8];
    const float* ups  = (const float*)d_in[9];
    const float* zeta = (const float*)d_in[10];
    const int*   rows = (const int*)d_in[11];
    const int*   cols = (const int*)d_in[12];
    float* out = (float*)d_out;

    prep_scatter_kernel<<<PREP_BLOCKS + SCAT_BLOCKS, 128>>>(
        C, D, M, cov, mu, nu, ups, zeta, bnz, anz, hnz, rows, cols);

    main_kernel<<<NC / 8, 256>>>(out);
}

// round 5
// speedup vs baseline: 1.4765x; 1.0904x over previous
#include <cuda_runtime.h>
#include <cuda_bf16.h>

#define NC   3144   // counties
#define TT   156    // time steps
#define TP   154    // predicted steps (T - p)
#define TPAD 160    // padded t dimension
#define NJ   80     // TPAD/2 float4 cells per column
#define NNZ  31440
#define CAP  128    // bucket capacity per column (Poisson(10), max ~35)

#define SCAT_BLOCKS 123                 // ceil(NNZ/256)
#define COV_BLOCKS  13                  // ceil(NC/256)
#define NMB         13                  // ceil(NC/256)
#define TC          4                   // t-steps per prep block
#define NTC         (TPAD / TC)         // 40
#define PREP_BLOCKS (NMB * NTC)         // 520

// -------- scratch (no allocations allowed; zero-initialized at load) --------
__device__ int    g_count[NC];
__device__ int4   g_meta[NC * CAP];     // {row, bv, av, hv}
__device__ float2 g_covb[NC];           // {ups@cov, zeta@cov} per column
__device__ float4 g_csd4[NC * NJ];      // {cs(2j), ds(2j), cs(2j+1), ds(2j+1)}
__device__ float4 g_base4[NC * NJ];     // mobility base, same packing

// ============================================================
// Kernel A: scatter (123 blk) + cov (13 blk) + prep (520 blk).
// Prep: 1 county/thread, TC=4 sequential t, rotating loads so
// C/D/M are read with only (TC+1)/TC redundancy.
// ============================================================
__global__ void prep_scatter_kernel(
    const float* __restrict__ C, const float* __restrict__ D,
    const float* __restrict__ M, const float* __restrict__ cov,
    const float* __restrict__ mu, const float* __restrict__ nu,
    const float* __restrict__ ups, const float* __restrict__ zeta,
    const float* __restrict__ bnz, const float* __restrict__ anz,
    const float* __restrict__ hnz, const int* __restrict__ rows,
    const int* __restrict__ cols)
{
    const int b  = blockIdx.x;
    const int tx = threadIdx.x;

    // ---------------- scatter ----------------
    if (b < SCAT_BLOCKS) {
        int k = b * 256 + tx;
        if (k < NNZ) {
            int c = cols[k];
            int slot = atomicAdd(&g_count[c], 1);
            if (slot < CAP)
                g_meta[c * CAP + slot] = make_int4(
                    rows[k], __float_as_int(bnz[k]),
                    __float_as_int(anz[k]), __float_as_int(hnz[k]));
        }
        return;
    }
    // ---------------- cov base ----------------
    if (b < SCAT_BLOCKS + COV_BLOCKS) {
        int m = (b - SCAT_BLOCKS) * 256 + tx;
        if (m < NC) {
            float a = 0.f, z = 0.f;
#pragma unroll
            for (int j = 0; j < 10; j++) {
                float cv = cov[j * NC + m];
                a += ups[j]  * cv;
                z += zeta[j] * cv;
            }
            g_covb[m] = make_float2(a, z);
        }
        return;
    }

    // ---------------- prep ----------------
    __shared__ float4 s_csd[256][2];
    __shared__ float4 s_bse[256][2];

    const int pb   = b - SCAT_BLOCKS - COV_BLOCKS;
    const int mblk = pb % NMB, tcb = pb / NMB;
    const int m0 = mblk * 256;
    const int m  = min(m0 + tx, NC - 1);
    const int t0 = tcb * TC;

    float muv[12], nuv[12];
#pragma unroll
    for (int i = 0; i < 12; i++) { muv[i] = mu[i]; nuv[i] = nu[i]; }

    // rotating "next" values: each t-level of C/D/M loaded once
    float cn = C[t0 * NC + m];
    float dn = D[t0 * NC + m];
    float mn[6];
#pragma unroll
    for (int k = 0; k < 6; k++) mn[k] = M[(k * TT + t0) * NC + m];

#pragma unroll
    for (int jj = 0; jj < 2; jj++) {
        float cs[2], ds[2], bc[2], bd[2];
#pragma unroll
        for (int sub = 0; sub < 2; sub++) {
            int tn = min(t0 + 2 * jj + sub + 1, TT - 1);  // t>=154 never stored
            float c0 = cn;  cn = C[tn * NC + m];
            float d0 = dn;  dn = D[tn * NC + m];
            cs[sub] = c0 + cn;
            ds[sub] = d0 + dn;
            float mc = 0.f, md = 0.f;
#pragma unroll
            for (int k = 0; k < 6; k++) {
                float v0 = mn[k];
                float v1 = M[(k * TT + tn) * NC + m];
                mn[k] = v1;
                mc += muv[k*2] * v0 + muv[k*2+1] * v1;
                md += nuv[k*2] * v0 + nuv[k*2+1] * v1;
            }
            bc[sub] = mc;
            bd[sub] = md;
        }
        s_csd[tx][jj] = make_float4(cs[0], ds[0], cs[1], ds[1]);
        s_bse[tx][jj] = make_float4(bc[0], bd[0], bc[1], bd[1]);
    }
    __syncthreads();

    // coalesced stores: consecutive threads -> consecutive float4
    const int j0 = t0 >> 1;
#pragma unroll
    for (int i = 0; i < 2; i++) {
        int idx = i * 256 + tx;            // 0..511
        int ml = idx >> 1, jl = idx & 1;
        if (m0 + ml < NC) {
            g_csd4 [(m0 + ml) * NJ + j0 + jl] = s_csd[ml][jl];
            g_base4[(m0 + ml) * NJ + j0 + jl] = s_bse[ml][jl];
        }
    }
}

// ============================================================
// Kernel B: sparse gather. 393 blocks x 512 thr (16 warps =
// 8 columns x 2 t-halves: 48/32 float4-cells split).
// ============================================================
__global__ void main_kernel(float* __restrict__ out)
{
    __shared__ int4   smeta[8][32];
    __shared__ float4 tile4[NJ][9];       // [j][m_local]

    const int tid  = threadIdx.x;
    const int w    = tid >> 5, lane = tid & 31;
    const int col  = w >> 1, half = w & 1;
    const int m0   = blockIdx.x * 8;
    const int m    = m0 + col;            // NC = 393*8 exact

    if (half == 0) smeta[col][lane] = g_meta[m * CAP + lane];
    const int cnt = g_count[m];           // broadcast; read BEFORE re-arm
    __syncthreads();
    if (half == 0 && lane == 0) g_count[m] = 0;   // re-arm for replay

    const float2 cv = g_covb[m];          // warp-uniform
    const int jn = min(cnt, 32);

    if (half == 0) {
        const int jA = lane, jB = 32 + lane;
        const bool actB = (lane < 16);
        float4 a0 = g_base4[m * NJ + jA];
        float4 a1 = make_float4(0.f, 0.f, 0.f, 0.f);
        if (actB) a1 = g_base4[m * NJ + jB];
        a0.x += cv.x; a0.y += cv.y; a0.z += cv.x; a0.w += cv.y;
        a1.x += cv.x; a1.y += cv.y; a1.z += cv.x; a1.w += cv.y;

#pragma unroll 4
        for (int j = 0; j < jn; j++) {
            int4 md = smeta[col][j];
            const float4* __restrict__ cr = &g_csd4[md.x * NJ];
            float bv = __int_as_float(md.y);
            float av = __int_as_float(md.z);
            float hv = __int_as_float(md.w);
            float4 v0 = cr[jA];
            a0.x += bv * v0.x;  a0.y += hv * v0.x + av * v0.y;
            a0.z += bv * v0.z;  a0.w += hv * v0.z + av * v0.w;
            if (actB) {
                float4 v1 = cr[jB];
                a1.x += bv * v1.x;  a1.y += hv * v1.x + av * v1.y;
                a1.z += bv * v1.z;  a1.w += hv * v1.z + av * v1.w;
            }
        }
        for (int s = 32; s < cnt; s++) {  // rare tail
            int4 md = g_meta[m * CAP + min(s, CAP - 1)];
            const float4* __restrict__ cr = &g_csd4[md.x * NJ];
            float bv = __int_as_float(md.y);
            float av = __int_as_float(md.z);
            float hv = __int_as_float(md.w);
            float4 v0 = cr[jA];
            a0.x += bv * v0.x;  a0.y += hv * v0.x + av * v0.y;
            a0.z += bv * v0.z;  a0.w += hv * v0.z + av * v0.w;
            if (actB) {
                float4 v1 = cr[jB];
                a1.x += bv * v1.x;  a1.y += hv * v1.x + av * v1.y;
                a1.z += bv * v1.z;  a1.w += hv * v1.z + av * v1.w;
            }
        }
        tile4[jA][col] = a0;
        if (actB) tile4[jB][col] = a1;
    } else {
        const int jA = 48 + lane;
        float4 a0 = g_base4[m * NJ + jA];
        a0.x += cv.x; a0.y += cv.y; a0.z += cv.x; a0.w += cv.y;

#pragma unroll 4
        for (int j = 0; j < jn; j++) {
            int4 md = smeta[col][j];
            const float4* __restrict__ cr = &g_csd4[md.x * NJ];
            float bv = __int_as_float(md.y);
            float av = __int_as_float(md.z);
            float hv = __int_as_float(md.w);
            float4 v0 = cr[jA];
            a0.x += bv * v0.x;  a0.y += hv * v0.x + av * v0.y;
            a0.z += bv * v0.z;  a0.w += hv * v0.z + av * v0.w;
        }
        for (int s = 32; s < cnt; s++) {
            int4 md = g_meta[m * CAP + min(s, CAP - 1)];
            const float4* __restrict__ cr = &g_csd4[md.x * NJ];
            float bv = __int_as_float(md.y);
            float av = __int_as_float(md.z);
            float hv = __int_as_float(md.w);
            float4 v0 = cr[jA];
            a0.x += bv * v0.x;  a0.y += hv * v0.x + av * v0.y;
            a0.z += bv * v0.z;  a0.w += hv * v0.z + av * v0.w;
        }
        tile4[jA][col] = a0;
    }
    __syncthreads();

    // coalesced output: 1280 (t, mo) cells over 512 threads
#pragma unroll
    for (int i = 0; i < 3; i++) {
        int idx = tid + i * 512;
        if (idx < TPAD * 8) {
            int t = idx >> 3, mo = idx & 7;
            if (t < TP) {
                float4 v = tile4[t >> 1][mo];
                float oc = (t & 1) ? v.z : v.x;
                float od = (t & 1) ? v.w : v.y;
                out[t        * NC + m0 + mo] = oc;
                out[(TP + t) * NC + m0 + mo] = od;
            }
        }
    }
}

// ============================================================
extern "C" void kernel_launch(void* const* d_in, const int* in_sizes, int n_in,
                              void* d_out, int out_size)
{
    const float* C    = (const float*)d_in[0];
    const float* D    = (const float*)d_in[1];
    const float* M    = (const float*)d_in[2];
    const float* cov  = (const float*)d_in[3];
    const float* bnz  = (const float*)d_in[4];
    const float* anz  = (const float*)d_in[5];
    const float* hnz  = (const float*)d_in[6];
    const float* mu   = (const float*)d_in[7];
    const float* nu   = (const float*)d_in[8];
    const float* ups  = (const float*)d_in[9];
    const float* zeta = (const float*)d_in[10];
    const int*   rows = (const int*)d_in[11];
    const int*   cols = (const int*)d_in[12];
    float* out = (float*)d_out;

    prep_scatter_kernel<<<SCAT_BLOCKS + COV_BLOCKS + PREP_BLOCKS, 256>>>(
        C, D, M, cov, mu, nu, ups, zeta, bnz, anz, hnz, rows, cols);

    main_kernel<<<NC / 8, 512>>>(out);
}